// round 15
// baseline (speedup 1.0000x reference)
#include <cuda_runtime.h>
#include <cuda_fp16.h>
#include <cstdint>
#include <cstddef>

#define EMB 1024
#define SEQ 2048
#define NB  4
#define NH  16
#define MR  (NB*SEQ)   // 8192 rows

// static device scratch (allocation-guard safe) — fp16 activations/weights
__device__ __half g_q [(size_t)MR*EMB];
__device__ __half g_k [(size_t)MR*EMB];
__device__ __half g_v [(size_t)MR*EMB];
__device__ __half g_ao[(size_t)MR*EMB];
__device__ __half g_xc[(size_t)MR*EMB];
__device__ __half g_wq[(size_t)EMB*EMB];
__device__ __half g_wk[(size_t)EMB*EMB];
__device__ __half g_wv[(size_t)EMB*EMB];
__device__ __half g_wo[(size_t)EMB*EMB];

__device__ __forceinline__ float ex2f(float x){
    float y; asm("ex2.approx.ftz.f32 %0, %1;" : "=f"(y) : "f"(x)); return y;
}
// D += A*B : m16n8k16 fp16 in / fp32 accum.
__device__ __forceinline__ void mma16(float* d, const uint32_t* a,
                                      uint32_t b0, uint32_t b1){
    asm volatile(
      "mma.sync.aligned.m16n8k16.row.col.f32.f16.f16.f32 "
      "{%0,%1,%2,%3}, {%4,%5,%6,%7}, {%8,%9}, {%0,%1,%2,%3};\n"
      : "+f"(d[0]), "+f"(d[1]), "+f"(d[2]), "+f"(d[3])
      : "r"(a[0]), "r"(a[1]), "r"(a[2]), "r"(a[3]), "r"(b0), "r"(b1));
}
__device__ __forceinline__ void ldsm4(uint32_t* r, uint32_t saddr){
    asm volatile("ldmatrix.sync.aligned.m8n8.x4.shared.b16 {%0,%1,%2,%3}, [%4];"
        : "=r"(r[0]), "=r"(r[1]), "=r"(r[2]), "=r"(r[3]) : "r"(saddr));
}
__device__ __forceinline__ void ldsm4t(uint32_t* r, uint32_t saddr){
    asm volatile("ldmatrix.sync.aligned.m8n8.x4.trans.shared.b16 {%0,%1,%2,%3}, [%4];"
        : "=r"(r[0]), "=r"(r[1]), "=r"(r[2]), "=r"(r[3]) : "r"(saddr));
}
__device__ __forceinline__ void cpa16(uint32_t saddr, const void* g){
    asm volatile("cp.async.ca.shared.global [%0], [%1], 16;" :: "r"(saddr), "l"(g));
}
__device__ __forceinline__ void cpa_commit(){ asm volatile("cp.async.commit_group;"); }
__device__ __forceinline__ void cpa_wait0(){ asm volatile("cp.async.wait_group 0;"); }
__device__ __forceinline__ void cpa_wait1(){ asm volatile("cp.async.wait_group 1;"); }
__device__ __forceinline__ uint32_t ph2(float lo, float hi){
    __half2 t = __floats2half2_rn(lo, hi);
    return *(uint32_t*)&t;
}

// ------------------------------------------------------------------
// Fused fp32 -> fp16 pre-round: one launch for x + 4 weights.
// ------------------------------------------------------------------
#define CVT_CH 262144   // float4 per chunk

__global__ void __launch_bounds__(256) cvt_all(
    const float4* __restrict__ x,
    const float4* __restrict__ Wq, const float4* __restrict__ Wk,
    const float4* __restrict__ Wv, const float4* __restrict__ Wo,
    uint2* __restrict__ xc,
    uint2* __restrict__ wq, uint2* __restrict__ wk,
    uint2* __restrict__ wv, uint2* __restrict__ wo)
{
    const int c = blockIdx.y;
    const float4* s; uint2* d;
    if (c < 8){ s = x + (size_t)c*CVT_CH; d = xc + (size_t)c*CVT_CH; }
    else if (c == 8){ s = Wq; d = wq; }
    else if (c == 9){ s = Wk; d = wk; }
    else if (c == 10){ s = Wv; d = wv; }
    else { s = Wo; d = wo; }

    int i0 = blockIdx.x*256 + threadIdx.x;
    int i1 = i0 + CVT_CH/2;
    float4 v0 = s[i0];
    float4 v1 = s[i1];
    uint2 o0, o1;
    o0.x = ph2(v0.x, v0.y); o0.y = ph2(v0.z, v0.w);
    o1.x = ph2(v1.x, v1.y); o1.y = ph2(v1.z, v1.w);
    d[i0] = o0;
    d[i1] = o1;
}

// ------------------------------------------------------------------
// fp16 GEMM: C[M,N] = A[M,K] @ W[N,K]^T (+bias). M=8192, N=K=1024.
// Block 128x128, BK=64, 128 thr (4 warps 2m x 2n, warp tile 64x64).
// 3-STAGE cp.async pipeline, ONE __syncthreads per k-tile:
//   iter kt: stage(kt+2 -> slot (kt+2)%3) ; compute slot kt%3 ;
//            wait(tile kt+1) ; sync.
// Slot (kt+2)%3 == (kt-1)%3 was computed last iter; all warps passed
// the end-of-iter sync, so it is free when staging begins.
// ------------------------------------------------------------------
#define RS   144                              // row stride bytes
#define GT_B (128*RS)                         // 18432 per operand tile
#define GSTG (2*GT_B)                         // 36864 per stage
#define GEMM_SMEM (3*GSTG)                    // 110592

__device__ __forceinline__ void gemm_body(
    const __half* __restrict__ A, const __half* __restrict__ W,
    const float* __restrict__ bias, void* __restrict__ C, int out_half)
{
    extern __shared__ uint32_t sh[];
    const uint32_t sbase = (uint32_t)__cvta_generic_to_shared(sh);

    const int tid  = threadIdx.x;
    const int lane = tid & 31, g = lane >> 2, tg = lane & 3;
    const int wid  = tid >> 5;                // 0..3
    const int wm   = (wid & 1) * 64;
    const int wn   = (wid >> 1) * 64;
    const int bm   = blockIdx.y * 128;
    const int bn   = blockIdx.x * 128;

    const int alr = lane & 15;
    const int alk = (lane >> 4) * 16;

    const __half* Ag = A + (size_t)bm*EMB;
    const __half* Wg = W + (size_t)bn*EMB;

    float acc[4][8][4];
#pragma unroll
    for (int mi = 0; mi < 4; mi++)
#pragma unroll
        for (int t = 0; t < 8; t++)
#pragma unroll
            for (int j = 0; j < 4; j++) acc[mi][t][j] = 0.f;

    auto stage = [&](int kt, int s){
        const uint32_t sa = sbase + (uint32_t)s*GSTG;
        const uint32_t sb = sa + GT_B;
#pragma unroll
        for (int i = 0; i < 8; i++){           // A: 128 rows x 8 chunks
            int id = tid + i*128, r = id >> 3, c = id & 7;
            cpa16(sa + r*RS + c*16, Ag + (size_t)r*EMB + kt*64 + c*8);
        }
#pragma unroll
        for (int i = 0; i < 8; i++){           // B: 128 rows x 8 chunks
            int id = tid + i*128, r = id >> 3, c = id & 7;
            cpa16(sb + r*RS + c*16, Wg + (size_t)r*EMB + kt*64 + c*8);
        }
        cpa_commit();
    };

    stage(0, 0);
    stage(1, 1);
    cpa_wait1();                // tile 0 arrived (tile 1 in flight)
    __syncthreads();

    const int nk = EMB/64;   // 16
    for (int kt = 0; kt < nk; kt++){
        const int s = kt % 3;
        if (kt + 2 < nk) stage(kt + 2, (kt + 2) % 3);
        const uint32_t sa = sbase + (uint32_t)s*GSTG;
        const uint32_t sb = sa + GT_B;
#pragma unroll
        for (int kk = 0; kk < 4; kk++){        // 4 x k16
            uint32_t af[4][4], bf[4][4];
#pragma unroll
            for (int mi = 0; mi < 4; mi++)
                ldsm4(af[mi], sa + (wm + mi*16 + alr)*RS + kk*32 + alk);
#pragma unroll
            for (int p = 0; p < 4; p++)
                ldsm4(bf[p], sb + (wn + p*16 + alr)*RS + kk*32 + alk);
#pragma unroll
            for (int mi = 0; mi < 4; mi++)
#pragma unroll
                for (int p = 0; p < 4; p++){
                    mma16(acc[mi][2*p],   af[mi], bf[p][0], bf[p][2]);
                    mma16(acc[mi][2*p+1], af[mi], bf[p][1], bf[p][3]);
                }
        }
        if (kt + 1 < nk){
            if (kt + 2 < nk) cpa_wait1(); else cpa_wait0();
            __syncthreads();   // tile kt+1 visible; slot kt%3 free next iter
        }
    }

    // epilogue
#pragma unroll
    for (int mi = 0; mi < 4; mi++){
#pragma unroll
        for (int t = 0; t < 8; t++){
            int col  = bn + wn + t*8 + 2*tg;
            int row0 = bm + wm + mi*16 + g;
            if (out_half){
                __half2 h0 = __floats2half2_rn(acc[mi][t][0], acc[mi][t][1]);
                __half2 h1 = __floats2half2_rn(acc[mi][t][2], acc[mi][t][3]);
                *(__half2*)((__half*)C + (size_t)row0      *EMB + col) = h0;
                *(__half2*)((__half*)C + (size_t)(row0 + 8)*EMB + col) = h1;
            } else {
                float b0 = bias ? bias[col]   : 0.f;
                float b1 = bias ? bias[col+1] : 0.f;
                float2 v0 = make_float2(acc[mi][t][0] + b0, acc[mi][t][1] + b1);
                float2 v1 = make_float2(acc[mi][t][2] + b0, acc[mi][t][3] + b1);
                *(float2*)((float*)C + (size_t)row0      *EMB + col) = v0;
                *(float2*)((float*)C + (size_t)(row0 + 8)*EMB + col) = v1;
            }
        }
    }
}

__global__ void __launch_bounds__(128, 2) gemm_qkv(
    const __half* __restrict__ x,
    const __half* __restrict__ Wq, const __half* __restrict__ Wk,
    const __half* __restrict__ Wv,
    __half* __restrict__ q, __half* __restrict__ k, __half* __restrict__ v)
{
    const __half* W = (blockIdx.z == 0) ? Wq : (blockIdx.z == 1) ? Wk : Wv;
    __half*       C = (blockIdx.z == 0) ? q  : (blockIdx.z == 1) ? k  : v;
    gemm_body(x, W, nullptr, C, 1);
}
__global__ void __launch_bounds__(128, 2) gemm_out(
    const __half* __restrict__ A, const __half* __restrict__ W,
    const float* __restrict__ bias, float* __restrict__ C)
{
    gemm_body(A, W, bias, C, 0);
}

// ------------------------------------------------------------------
// Flash attention v2 (causal), fp16 operands / fp32 softmax+accum.
// grid(16, B*H), 256 threads (8 warps), q-tile 128, 16 q-rows/warp.
// Q frags hoisted. 3-STAGE K/V pipeline, ONE sync per key tile
// (same slot-freshness argument as the GEMM).
// ------------------------------------------------------------------
#define QS_B (128*RS)      // 18432
#define KS_B (64*RS)       //  9216
#define ATTN_SMEM (QS_B + 6*KS_B)   // 73728

__global__ void __launch_bounds__(256, 2) attn_kernel(
    const __half* __restrict__ Q, const __half* __restrict__ K,
    const __half* __restrict__ V, __half* __restrict__ O)
{
    extern __shared__ uint32_t dyn[];
    const uint32_t sbase = (uint32_t)__cvta_generic_to_shared(dyn);
    const uint32_t qsa = sbase;

    const int tid  = threadIdx.x;
    const int lane = tid & 31, g = lane >> 2, tg = lane & 3;
    const int wq   = tid >> 5;
    const int qt   = gridDim.x - 1 - blockIdx.x;    // heavy blocks first
    const int b    = blockIdx.y >> 4;
    const int h    = blockIdx.y & 15;
    const int qbase = qt * 128;
    const float cs = 0.125f * 1.44269504088896f;    // 1/sqrt(64)*log2(e)

    const int alr = lane & 15, alk = (lane >> 4) * 16;

    const __half* Qg = Q + (size_t)(b*SEQ + qbase)*EMB + h*64;
    const __half* Kg = K + (size_t)(b*SEQ)*EMB + h*64;
    const __half* Vg = V + (size_t)(b*SEQ)*EMB + h*64;

    auto kbuf = [&](int s){ return sbase + QS_B + (uint32_t)s*(2*KS_B); };
    auto vbuf = [&](int s){ return sbase + QS_B + (uint32_t)s*(2*KS_B) + KS_B; };

    auto load_kv = [&](int jt, int s){
        uint32_t ka = kbuf(s), va = vbuf(s);
#pragma unroll
        for (int i = 0; i < 2; i++){
            int id = tid + i*256, r = id >> 3, c = id & 7;
            cpa16(ka + r*RS + c*16, Kg + (size_t)(jt*64 + r)*EMB + c*8);
        }
#pragma unroll
        for (int i = 0; i < 2; i++){
            int id = tid + i*256, r = id >> 3, c = id & 7;
            cpa16(va + r*RS + c*16, Vg + (size_t)(jt*64 + r)*EMB + c*8);
        }
    };

    const int njt = 2*qt + 2;     // always >= 2

    // prologue: G0 = Q + kv0 ; G1 = kv1 ; wait tile0, sync, load qf
#pragma unroll
    for (int i = 0; i < 4; i++){
        int id = tid + i*256, r = id >> 3, c = id & 7;
        cpa16(qsa + r*RS + c*16, Qg + (size_t)r*EMB + c*8);
    }
    load_kv(0, 0);
    cpa_commit();
    load_kv(1, 1);
    cpa_commit();
    cpa_wait1();
    __syncthreads();

    uint32_t qf[4][4];           // Q A-frags, loop-invariant
#pragma unroll
    for (int ks = 0; ks < 4; ks++)
        ldsm4(qf[ks], qsa + (wq*16 + alr)*RS + ks*32 + alk);

    float m0 = -1e30f, m1 = -1e30f, l0 = 0.f, l1 = 0.f;
    float o[8][4];
#pragma unroll
    for (int t = 0; t < 8; t++)
#pragma unroll
        for (int j = 0; j < 4; j++) o[t][j] = 0.f;

    const int q0r = qbase + wq*16 + g;
    const int q1r = q0r + 8;

    for (int jt = 0; jt < njt; jt++){
        const int s = jt % 3;
        if (jt + 2 < njt){ load_kv(jt + 2, (jt + 2) % 3); cpa_commit(); }
        const uint32_t ka = kbuf(s), va = vbuf(s);

        // ---- S = Q @ K^T : 16 q-rows x 64 keys per warp (raw scores)
        float sacc[8][4];
#pragma unroll
        for (int t = 0; t < 8; t++)
#pragma unroll
            for (int j = 0; j < 4; j++) sacc[t][j] = 0.f;
#pragma unroll
        for (int ks = 0; ks < 4; ks++){
            uint32_t bk[4][4];
#pragma unroll
            for (int p = 0; p < 4; p++)
                ldsm4(bk[p], ka + (p*16 + alr)*RS + ks*32 + alk);
#pragma unroll
            for (int p = 0; p < 4; p++){
                mma16(sacc[2*p],   qf[ks], bk[p][0], bk[p][2]);
                mma16(sacc[2*p+1], qf[ks], bk[p][1], bk[p][3]);
            }
        }

        // ---- causal mask (raw) + online softmax (max in raw domain)
        const bool need_mask = (jt >= 2*qt);
        {
            float tm0 = -1e30f, tm1 = -1e30f;
#pragma unroll
            for (int t = 0; t < 8; t++){
                float* sc = sacc[t];
                if (need_mask){
                    int jc = jt*64 + t*8 + 2*tg;
                    if (jc     > q0r) sc[0] = -1e30f;
                    if (jc + 1 > q0r) sc[1] = -1e30f;
                    if (jc     > q1r) sc[2] = -1e30f;
                    if (jc + 1 > q1r) sc[3] = -1e30f;
                }
                tm0 = fmaxf(tm0, fmaxf(sc[0], sc[1]));
                tm1 = fmaxf(tm1, fmaxf(sc[2], sc[3]));
            }
            tm0 = fmaxf(tm0, __shfl_xor_sync(0xffffffffu, tm0, 1));
            tm0 = fmaxf(tm0, __shfl_xor_sync(0xffffffffu, tm0, 2));
            tm1 = fmaxf(tm1, __shfl_xor_sync(0xffffffffu, tm1, 1));
            tm1 = fmaxf(tm1, __shfl_xor_sync(0xffffffffu, tm1, 2));
            float mn0 = fmaxf(m0, tm0 * cs);
            float mn1 = fmaxf(m1, tm1 * cs);
            float a0  = ex2f(m0 - mn0);
            float a1  = ex2f(m1 - mn1);
            float rs0 = 0.f, rs1 = 0.f;
#pragma unroll
            for (int t = 0; t < 8; t++){
                float* sc = sacc[t];
                sc[0] = ex2f(fmaf(sc[0], cs, -mn0));
                sc[1] = ex2f(fmaf(sc[1], cs, -mn0));
                sc[2] = ex2f(fmaf(sc[2], cs, -mn1));
                sc[3] = ex2f(fmaf(sc[3], cs, -mn1));
                rs0 += sc[0] + sc[1];
                rs1 += sc[2] + sc[3];
            }
            rs0 += __shfl_xor_sync(0xffffffffu, rs0, 1);
            rs0 += __shfl_xor_sync(0xffffffffu, rs0, 2);
            rs1 += __shfl_xor_sync(0xffffffffu, rs1, 1);
            rs1 += __shfl_xor_sync(0xffffffffu, rs1, 2);
            l0 = l0*a0 + rs0;
            l1 = l1*a1 + rs1;
            m0 = mn0; m1 = mn1;
#pragma unroll
            for (int t = 0; t < 8; t++){
                o[t][0] *= a0; o[t][1] *= a0;
                o[t][2] *= a1; o[t][3] *= a1;
            }
        }

        // ---- O += P @ V : B-frags via ldmatrix.trans on row-major V
#pragma unroll
        for (int ks = 0; ks < 4; ks++){
            uint32_t av[4];
            av[0] = ph2(sacc[2*ks][0],   sacc[2*ks][1]);
            av[1] = ph2(sacc[2*ks][2],   sacc[2*ks][3]);
            av[2] = ph2(sacc[2*ks+1][0], sacc[2*ks+1][1]);
            av[3] = ph2(sacc[2*ks+1][2], sacc[2*ks+1][3]);
#pragma unroll
            for (int p = 0; p < 4; p++){
                uint32_t bv[4];
                ldsm4t(bv, va + (ks*16 + alr)*RS + p*32 + alk);
                mma16(o[2*p],   av, bv[0], bv[1]);
                mma16(o[2*p+1], av, bv[2], bv[3]);
            }
        }

        // ---- single sync per tile: tile jt+1 visible, slot jt%3 freed
        if (jt + 1 < njt){
            if (jt + 2 < njt) cpa_wait1(); else cpa_wait0();
            __syncthreads();
        }
    }

    // ---- epilogue: normalize, store half (feeds final GEMM)
    {
        float i0 = 1.f / l0;
        float i1 = 1.f / l1;
        size_t r0 = (size_t)(b*SEQ + q0r);
#pragma unroll
        for (int t = 0; t < 8; t++){
            int col = h*64 + t*8 + 2*tg;
            __half2 h0 = __floats2half2_rn(o[t][0]*i0, o[t][1]*i0);
            __half2 h1 = __floats2half2_rn(o[t][2]*i1, o[t][3]*i1);
            *(__half2*)(O + r0*EMB + col)       = h0;
            *(__half2*)(O + (r0 + 8)*EMB + col) = h1;
        }
    }
}

// ------------------------------------------------------------------
extern "C" void kernel_launch(void* const* d_in, const int* in_sizes, int n_in,
                              void* d_out, int out_size)
{
    const float* x  = (const float*)d_in[0];
    const float* Wq = (const float*)d_in[1];
    const float* Wk = (const float*)d_in[2];
    const float* Wv = (const float*)d_in[3];
    const float* Wo = (const float*)d_in[4];
    const float* bo = (const float*)d_in[5];
    float* out = (float*)d_out;

    __half *q, *k, *v, *ao, *xc, *wq, *wk, *wv, *wo;
    cudaGetSymbolAddress((void**)&q,  g_q);
    cudaGetSymbolAddress((void**)&k,  g_k);
    cudaGetSymbolAddress((void**)&v,  g_v);
    cudaGetSymbolAddress((void**)&ao, g_ao);
    cudaGetSymbolAddress((void**)&xc, g_xc);
    cudaGetSymbolAddress((void**)&wq, g_wq);
    cudaGetSymbolAddress((void**)&wk, g_wk);
    cudaGetSymbolAddress((void**)&wv, g_wv);
    cudaGetSymbolAddress((void**)&wo, g_wo);

    cudaFuncSetAttribute(gemm_qkv,
                         cudaFuncAttributeMaxDynamicSharedMemorySize, GEMM_SMEM);
    cudaFuncSetAttribute(gemm_out,
                         cudaFuncAttributeMaxDynamicSharedMemorySize, GEMM_SMEM);
    cudaFuncSetAttribute(attn_kernel,
                         cudaFuncAttributeMaxDynamicSharedMemorySize, ATTN_SMEM);

    // fused fp32->fp16 pre-round (x: 8 chunks, weights: 1 chunk each)
    dim3 gc(CVT_CH/(256*2), 12);          // 512 x 12
    cvt_all<<<gc, 256>>>((const float4*)x,
                         (const float4*)Wq, (const float4*)Wk,
                         (const float4*)Wv, (const float4*)Wo,
                         (uint2*)xc, (uint2*)wq, (uint2*)wk,
                         (uint2*)wv, (uint2*)wo);

    dim3 gq(EMB/128, MR/128, 3);          // 8 x 64 x 3
    gemm_qkv<<<gq, 128, GEMM_SMEM>>>(xc, wq, wk, wv, q, k, v);

    dim3 ga(SEQ/128, NB*NH);              // 16 x 64
    attn_kernel<<<ga, 256, ATTN_SMEM>>>(q, k, v, ao);

    dim3 go(EMB/128, MR/128);             // 8 x 64
    gemm_out<<<go, 128, GEMM_SMEM>>>(ao, wo, bo, out);
}

// round 16
// speedup vs baseline: 1.0339x; 1.0339x over previous
#include <cuda_runtime.h>
#include <cuda_fp16.h>
#include <cstdint>
#include <cstddef>

#define EMB 1024
#define SEQ 2048
#define NB  4
#define NH  16
#define MR  (NB*SEQ)   // 8192 rows

// static device scratch (allocation-guard safe) — fp16 activations/weights
__device__ __half g_q [(size_t)MR*EMB];
__device__ __half g_k [(size_t)MR*EMB];
__device__ __half g_v [(size_t)MR*EMB];
__device__ __half g_ao[(size_t)MR*EMB];
__device__ __half g_xc[(size_t)MR*EMB];
__device__ __half g_wq[(size_t)EMB*EMB];
__device__ __half g_wk[(size_t)EMB*EMB];
__device__ __half g_wv[(size_t)EMB*EMB];
__device__ __half g_wo[(size_t)EMB*EMB];

__device__ __forceinline__ float ex2f(float x){
    float y; asm("ex2.approx.ftz.f32 %0, %1;" : "=f"(y) : "f"(x)); return y;
}
// D += A*B : m16n8k16 fp16 in / fp32 accum.
__device__ __forceinline__ void mma16(float* d, const uint32_t* a,
                                      uint32_t b0, uint32_t b1){
    asm volatile(
      "mma.sync.aligned.m16n8k16.row.col.f32.f16.f16.f32 "
      "{%0,%1,%2,%3}, {%4,%5,%6,%7}, {%8,%9}, {%0,%1,%2,%3};\n"
      : "+f"(d[0]), "+f"(d[1]), "+f"(d[2]), "+f"(d[3])
      : "r"(a[0]), "r"(a[1]), "r"(a[2]), "r"(a[3]), "r"(b0), "r"(b1));
}
__device__ __forceinline__ void ldsm4(uint32_t* r, uint32_t saddr){
    asm volatile("ldmatrix.sync.aligned.m8n8.x4.shared.b16 {%0,%1,%2,%3}, [%4];"
        : "=r"(r[0]), "=r"(r[1]), "=r"(r[2]), "=r"(r[3]) : "r"(saddr));
}
__device__ __forceinline__ void ldsm4t(uint32_t* r, uint32_t saddr){
    asm volatile("ldmatrix.sync.aligned.m8n8.x4.trans.shared.b16 {%0,%1,%2,%3}, [%4];"
        : "=r"(r[0]), "=r"(r[1]), "=r"(r[2]), "=r"(r[3]) : "r"(saddr));
}
__device__ __forceinline__ void cpa16(uint32_t saddr, const void* g){
    asm volatile("cp.async.ca.shared.global [%0], [%1], 16;" :: "r"(saddr), "l"(g));
}
__device__ __forceinline__ void cpa_commit(){ asm volatile("cp.async.commit_group;"); }
__device__ __forceinline__ void cpa_wait0(){ asm volatile("cp.async.wait_group 0;"); }
__device__ __forceinline__ void cpa_wait1(){ asm volatile("cp.async.wait_group 1;"); }
__device__ __forceinline__ uint32_t ph2(float lo, float hi){
    __half2 t = __floats2half2_rn(lo, hi);
    return *(uint32_t*)&t;
}

// ------------------------------------------------------------------
// Fused fp32 -> fp16 pre-round: one launch for x + 4 weights.
// ------------------------------------------------------------------
#define CVT_CH 262144   // float4 per chunk

__global__ void __launch_bounds__(256) cvt_all(
    const float4* __restrict__ x,
    const float4* __restrict__ Wq, const float4* __restrict__ Wk,
    const float4* __restrict__ Wv, const float4* __restrict__ Wo,
    uint2* __restrict__ xc,
    uint2* __restrict__ wq, uint2* __restrict__ wk,
    uint2* __restrict__ wv, uint2* __restrict__ wo)
{
    const int c = blockIdx.y;
    const float4* s; uint2* d;
    if (c < 8){ s = x + (size_t)c*CVT_CH; d = xc + (size_t)c*CVT_CH; }
    else if (c == 8){ s = Wq; d = wq; }
    else if (c == 9){ s = Wk; d = wk; }
    else if (c == 10){ s = Wv; d = wv; }
    else { s = Wo; d = wo; }

    int i0 = blockIdx.x*256 + threadIdx.x;
    int i1 = i0 + CVT_CH/2;
    float4 v0 = s[i0];
    float4 v1 = s[i1];
    uint2 o0, o1;
    o0.x = ph2(v0.x, v0.y); o0.y = ph2(v0.z, v0.w);
    o1.x = ph2(v1.x, v1.y); o1.y = ph2(v1.z, v1.w);
    d[i0] = o0;
    d[i1] = o1;
}

// ------------------------------------------------------------------
// fp16 GEMM: C[M,N] = A[M,K] @ W[N,K]^T (+bias). M=8192, N=K=1024.
// Block 128x128, BK=64, 128 thr (4 warps 2m x 2n, warp tile 64x64).
// 3-stage pipeline, ONE sync per tile, staging AFTER compute:
//   iter kt: compute slot kt%3 ; stage(kt+2 -> (kt+2)%3) ; wait1 ; sync
// Slot (kt+2)%3 == (kt-1)%3 was computed at kt-1 and synced -> safe.
// cp.async issue overlaps the wait instead of delaying ldsm (R15 bug).
// ------------------------------------------------------------------
#define RS   144                              // row stride bytes
#define GT_B (128*RS)                         // 18432 per operand tile
#define GSTG (2*GT_B)                         // 36864 per stage
#define GEMM_SMEM (3*GSTG)                    // 110592

__device__ __forceinline__ void gemm_body(
    const __half* __restrict__ A, const __half* __restrict__ W,
    const float* __restrict__ bias, void* __restrict__ C, int out_half)
{
    extern __shared__ uint32_t sh[];
    const uint32_t sbase = (uint32_t)__cvta_generic_to_shared(sh);

    const int tid  = threadIdx.x;
    const int lane = tid & 31, g = lane >> 2, tg = lane & 3;
    const int wid  = tid >> 5;                // 0..3
    const int wm   = (wid & 1) * 64;
    const int wn   = (wid >> 1) * 64;
    const int bm   = blockIdx.y * 128;
    const int bn   = blockIdx.x * 128;

    const int alr = lane & 15;
    const int alk = (lane >> 4) * 16;

    const __half* Ag = A + (size_t)bm*EMB;
    const __half* Wg = W + (size_t)bn*EMB;

    float acc[4][8][4];
#pragma unroll
    for (int mi = 0; mi < 4; mi++)
#pragma unroll
        for (int t = 0; t < 8; t++)
#pragma unroll
            for (int j = 0; j < 4; j++) acc[mi][t][j] = 0.f;

    auto stage = [&](int kt, int s){
        const uint32_t sa = sbase + (uint32_t)s*GSTG;
        const uint32_t sb = sa + GT_B;
#pragma unroll
        for (int i = 0; i < 8; i++){           // A: 128 rows x 8 chunks
            int id = tid + i*128, r = id >> 3, c = id & 7;
            cpa16(sa + r*RS + c*16, Ag + (size_t)r*EMB + kt*64 + c*8);
        }
#pragma unroll
        for (int i = 0; i < 8; i++){           // B: 128 rows x 8 chunks
            int id = tid + i*128, r = id >> 3, c = id & 7;
            cpa16(sb + r*RS + c*16, Wg + (size_t)r*EMB + kt*64 + c*8);
        }
        cpa_commit();
    };

    stage(0, 0);
    stage(1, 1);
    cpa_wait1();                // tile 0 arrived (tile 1 in flight)
    __syncthreads();

    const int nk = EMB/64;   // 16
    for (int kt = 0; kt < nk; kt++){
        const int s = kt % 3;
        const uint32_t sa = sbase + (uint32_t)s*GSTG;
        const uint32_t sb = sa + GT_B;
#pragma unroll
        for (int kk = 0; kk < 4; kk++){        // 4 x k16
            uint32_t af[4][4], bf[4][4];
#pragma unroll
            for (int mi = 0; mi < 4; mi++)
                ldsm4(af[mi], sa + (wm + mi*16 + alr)*RS + kk*32 + alk);
#pragma unroll
            for (int p = 0; p < 4; p++)
                ldsm4(bf[p], sb + (wn + p*16 + alr)*RS + kk*32 + alk);
#pragma unroll
            for (int mi = 0; mi < 4; mi++)
#pragma unroll
                for (int p = 0; p < 4; p++){
                    mma16(acc[mi][2*p],   af[mi], bf[p][0], bf[p][2]);
                    mma16(acc[mi][2*p+1], af[mi], bf[p][1], bf[p][3]);
                }
        }
        if (kt + 2 < nk) stage(kt + 2, (kt + 2) % 3);
        if (kt + 1 < nk){
            if (kt + 2 < nk) cpa_wait1(); else cpa_wait0();
            __syncthreads();   // tile kt+1 visible; slot freshness per header
        }
    }

    // epilogue
#pragma unroll
    for (int mi = 0; mi < 4; mi++){
#pragma unroll
        for (int t = 0; t < 8; t++){
            int col  = bn + wn + t*8 + 2*tg;
            int row0 = bm + wm + mi*16 + g;
            if (out_half){
                __half2 h0 = __floats2half2_rn(acc[mi][t][0], acc[mi][t][1]);
                __half2 h1 = __floats2half2_rn(acc[mi][t][2], acc[mi][t][3]);
                *(__half2*)((__half*)C + (size_t)row0      *EMB + col) = h0;
                *(__half2*)((__half*)C + (size_t)(row0 + 8)*EMB + col) = h1;
            } else {
                float b0 = bias ? bias[col]   : 0.f;
                float b1 = bias ? bias[col+1] : 0.f;
                float2 v0 = make_float2(acc[mi][t][0] + b0, acc[mi][t][1] + b1);
                float2 v1 = make_float2(acc[mi][t][2] + b0, acc[mi][t][3] + b1);
                *(float2*)((float*)C + (size_t)row0      *EMB + col) = v0;
                *(float2*)((float*)C + (size_t)(row0 + 8)*EMB + col) = v1;
            }
        }
    }
}

__global__ void __launch_bounds__(128, 2) gemm_qkv(
    const __half* __restrict__ x,
    const __half* __restrict__ Wq, const __half* __restrict__ Wk,
    const __half* __restrict__ Wv,
    __half* __restrict__ q, __half* __restrict__ k, __half* __restrict__ v)
{
    const __half* W = (blockIdx.z == 0) ? Wq : (blockIdx.z == 1) ? Wk : Wv;
    __half*       C = (blockIdx.z == 0) ? q  : (blockIdx.z == 1) ? k  : v;
    gemm_body(x, W, nullptr, C, 1);
}
__global__ void __launch_bounds__(128, 2) gemm_out(
    const __half* __restrict__ A, const __half* __restrict__ W,
    const float* __restrict__ bias, float* __restrict__ C)
{
    gemm_body(A, W, bias, C, 0);
}

// ------------------------------------------------------------------
// Flash attention v2 (causal), fp16 operands / fp32 softmax+accum.
// grid(16, B*H), 256 threads (8 warps), q-tile 128, 16 q-rows/warp.
// Q frags hoisted. 3-stage K/V pipeline, ONE sync per key tile,
// staging AFTER compute (same ordering fix as the GEMM).
// ------------------------------------------------------------------
#define QS_B (128*RS)      // 18432
#define KS_B (64*RS)       //  9216
#define ATTN_SMEM (QS_B + 6*KS_B)   // 73728

__global__ void __launch_bounds__(256, 2) attn_kernel(
    const __half* __restrict__ Q, const __half* __restrict__ K,
    const __half* __restrict__ V, __half* __restrict__ O)
{
    extern __shared__ uint32_t dyn[];
    const uint32_t sbase = (uint32_t)__cvta_generic_to_shared(dyn);
    const uint32_t qsa = sbase;

    const int tid  = threadIdx.x;
    const int lane = tid & 31, g = lane >> 2, tg = lane & 3;
    const int wq   = tid >> 5;
    const int qt   = gridDim.x - 1 - blockIdx.x;    // heavy blocks first
    const int b    = blockIdx.y >> 4;
    const int h    = blockIdx.y & 15;
    const int qbase = qt * 128;
    const float cs = 0.125f * 1.44269504088896f;    // 1/sqrt(64)*log2(e)

    const int alr = lane & 15, alk = (lane >> 4) * 16;

    const __half* Qg = Q + (size_t)(b*SEQ + qbase)*EMB + h*64;
    const __half* Kg = K + (size_t)(b*SEQ)*EMB + h*64;
    const __half* Vg = V + (size_t)(b*SEQ)*EMB + h*64;

    auto kbuf = [&](int s){ return sbase + QS_B + (uint32_t)s*(2*KS_B); };
    auto vbuf = [&](int s){ return sbase + QS_B + (uint32_t)s*(2*KS_B) + KS_B; };

    auto load_kv = [&](int jt, int s){
        uint32_t ka = kbuf(s), va = vbuf(s);
#pragma unroll
        for (int i = 0; i < 2; i++){
            int id = tid + i*256, r = id >> 3, c = id & 7;
            cpa16(ka + r*RS + c*16, Kg + (size_t)(jt*64 + r)*EMB + c*8);
        }
#pragma unroll
        for (int i = 0; i < 2; i++){
            int id = tid + i*256, r = id >> 3, c = id & 7;
            cpa16(va + r*RS + c*16, Vg + (size_t)(jt*64 + r)*EMB + c*8);
        }
    };

    const int njt = 2*qt + 2;     // always >= 2

    // prologue: G0 = Q + kv0 ; G1 = kv1 ; wait tile0, sync, load qf
#pragma unroll
    for (int i = 0; i < 4; i++){
        int id = tid + i*256, r = id >> 3, c = id & 7;
        cpa16(qsa + r*RS + c*16, Qg + (size_t)r*EMB + c*8);
    }
    load_kv(0, 0);
    cpa_commit();
    load_kv(1, 1);
    cpa_commit();
    cpa_wait1();
    __syncthreads();

    uint32_t qf[4][4];           // Q A-frags, loop-invariant
#pragma unroll
    for (int ks = 0; ks < 4; ks++)
        ldsm4(qf[ks], qsa + (wq*16 + alr)*RS + ks*32 + alk);

    float m0 = -1e30f, m1 = -1e30f, l0 = 0.f, l1 = 0.f;
    float o[8][4];
#pragma unroll
    for (int t = 0; t < 8; t++)
#pragma unroll
        for (int j = 0; j < 4; j++) o[t][j] = 0.f;

    const int q0r = qbase + wq*16 + g;
    const int q1r = q0r + 8;

    for (int jt = 0; jt < njt; jt++){
        const int s = jt % 3;
        const uint32_t ka = kbuf(s), va = vbuf(s);

        // ---- S = Q @ K^T : 16 q-rows x 64 keys per warp (raw scores)
        float sacc[8][4];
#pragma unroll
        for (int t = 0; t < 8; t++)
#pragma unroll
            for (int j = 0; j < 4; j++) sacc[t][j] = 0.f;
#pragma unroll
        for (int ks = 0; ks < 4; ks++){
            uint32_t bk[4][4];
#pragma unroll
            for (int p = 0; p < 4; p++)
                ldsm4(bk[p], ka + (p*16 + alr)*RS + ks*32 + alk);
#pragma unroll
            for (int p = 0; p < 4; p++){
                mma16(sacc[2*p],   qf[ks], bk[p][0], bk[p][2]);
                mma16(sacc[2*p+1], qf[ks], bk[p][1], bk[p][3]);
            }
        }

        // ---- causal mask (raw) + online softmax (max in raw domain)
        const bool need_mask = (jt >= 2*qt);
        {
            float tm0 = -1e30f, tm1 = -1e30f;
#pragma unroll
            for (int t = 0; t < 8; t++){
                float* sc = sacc[t];
                if (need_mask){
                    int jc = jt*64 + t*8 + 2*tg;
                    if (jc     > q0r) sc[0] = -1e30f;
                    if (jc + 1 > q0r) sc[1] = -1e30f;
                    if (jc     > q1r) sc[2] = -1e30f;
                    if (jc + 1 > q1r) sc[3] = -1e30f;
                }
                tm0 = fmaxf(tm0, fmaxf(sc[0], sc[1]));
                tm1 = fmaxf(tm1, fmaxf(sc[2], sc[3]));
            }
            tm0 = fmaxf(tm0, __shfl_xor_sync(0xffffffffu, tm0, 1));
            tm0 = fmaxf(tm0, __shfl_xor_sync(0xffffffffu, tm0, 2));
            tm1 = fmaxf(tm1, __shfl_xor_sync(0xffffffffu, tm1, 1));
            tm1 = fmaxf(tm1, __shfl_xor_sync(0xffffffffu, tm1, 2));
            float mn0 = fmaxf(m0, tm0 * cs);
            float mn1 = fmaxf(m1, tm1 * cs);
            float a0  = ex2f(m0 - mn0);
            float a1  = ex2f(m1 - mn1);
            float rs0 = 0.f, rs1 = 0.f;
#pragma unroll
            for (int t = 0; t < 8; t++){
                float* sc = sacc[t];
                sc[0] = ex2f(fmaf(sc[0], cs, -mn0));
                sc[1] = ex2f(fmaf(sc[1], cs, -mn0));
                sc[2] = ex2f(fmaf(sc[2], cs, -mn1));
                sc[3] = ex2f(fmaf(sc[3], cs, -mn1));
                rs0 += sc[0] + sc[1];
                rs1 += sc[2] + sc[3];
            }
            rs0 += __shfl_xor_sync(0xffffffffu, rs0, 1);
            rs0 += __shfl_xor_sync(0xffffffffu, rs0, 2);
            rs1 += __shfl_xor_sync(0xffffffffu, rs1, 1);
            rs1 += __shfl_xor_sync(0xffffffffu, rs1, 2);
            l0 = l0*a0 + rs0;
            l1 = l1*a1 + rs1;
            m0 = mn0; m1 = mn1;
#pragma unroll
            for (int t = 0; t < 8; t++){
                o[t][0] *= a0; o[t][1] *= a0;
                o[t][2] *= a1; o[t][3] *= a1;
            }
        }

        // ---- O += P @ V : B-frags via ldmatrix.trans on row-major V
#pragma unroll
        for (int ks = 0; ks < 4; ks++){
            uint32_t av[4];
            av[0] = ph2(sacc[2*ks][0],   sacc[2*ks][1]);
            av[1] = ph2(sacc[2*ks][2],   sacc[2*ks][3]);
            av[2] = ph2(sacc[2*ks+1][0], sacc[2*ks+1][1]);
            av[3] = ph2(sacc[2*ks+1][2], sacc[2*ks+1][3]);
#pragma unroll
            for (int p = 0; p < 4; p++){
                uint32_t bv[4];
                ldsm4t(bv, va + (ks*16 + alr)*RS + p*32 + alk);
                mma16(o[2*p],   av, bv[0], bv[1]);
                mma16(o[2*p+1], av, bv[2], bv[3]);
            }
        }

        // ---- stage jt+2 AFTER compute, then single wait+sync per tile
        if (jt + 2 < njt){ load_kv(jt + 2, (jt + 2) % 3); cpa_commit(); }
        if (jt + 1 < njt){
            if (jt + 2 < njt) cpa_wait1(); else cpa_wait0();
            __syncthreads();
        }
    }

    // ---- epilogue: normalize, store half (feeds final GEMM)
    {
        float i0 = 1.f / l0;
        float i1 = 1.f / l1;
        size_t r0 = (size_t)(b*SEQ + q0r);
#pragma unroll
        for (int t = 0; t < 8; t++){
            int col = h*64 + t*8 + 2*tg;
            __half2 h0 = __floats2half2_rn(o[t][0]*i0, o[t][1]*i0);
            __half2 h1 = __floats2half2_rn(o[t][2]*i1, o[t][3]*i1);
            *(__half2*)(O + r0*EMB + col)       = h0;
            *(__half2*)(O + (r0 + 8)*EMB + col) = h1;
        }
    }
}

// ------------------------------------------------------------------
extern "C" void kernel_launch(void* const* d_in, const int* in_sizes, int n_in,
                              void* d_out, int out_size)
{
    const float* x  = (const float*)d_in[0];
    const float* Wq = (const float*)d_in[1];
    const float* Wk = (const float*)d_in[2];
    const float* Wv = (const float*)d_in[3];
    const float* Wo = (const float*)d_in[4];
    const float* bo = (const float*)d_in[5];
    float* out = (float*)d_out;

    __half *q, *k, *v, *ao, *xc, *wq, *wk, *wv, *wo;
    cudaGetSymbolAddress((void**)&q,  g_q);
    cudaGetSymbolAddress((void**)&k,  g_k);
    cudaGetSymbolAddress((void**)&v,  g_v);
    cudaGetSymbolAddress((void**)&ao, g_ao);
    cudaGetSymbolAddress((void**)&xc, g_xc);
    cudaGetSymbolAddress((void**)&wq, g_wq);
    cudaGetSymbolAddress((void**)&wk, g_wk);
    cudaGetSymbolAddress((void**)&wv, g_wv);
    cudaGetSymbolAddress((void**)&wo, g_wo);

    cudaFuncSetAttribute(gemm_qkv,
                         cudaFuncAttributeMaxDynamicSharedMemorySize, GEMM_SMEM);
    cudaFuncSetAttribute(gemm_out,
                         cudaFuncAttributeMaxDynamicSharedMemorySize, GEMM_SMEM);
    cudaFuncSetAttribute(attn_kernel,
                         cudaFuncAttributeMaxDynamicSharedMemorySize, ATTN_SMEM);

    // fused fp32->fp16 pre-round (x: 8 chunks, weights: 1 chunk each)
    dim3 gc(CVT_CH/(256*2), 12);          // 512 x 12
    cvt_all<<<gc, 256>>>((const float4*)x,
                         (const float4*)Wq, (const float4*)Wk,
                         (const float4*)Wv, (const float4*)Wo,
                         (uint2*)xc, (uint2*)wq, (uint2*)wk,
                         (uint2*)wv, (uint2*)wo);

    dim3 gq(EMB/128, MR/128, 3);          // 8 x 64 x 3
    gemm_qkv<<<gq, 128, GEMM_SMEM>>>(xc, wq, wk, wv, q, k, v);

    dim3 ga(SEQ/128, NB*NH);              // 16 x 64
    attn_kernel<<<ga, 256, ATTN_SMEM>>>(q, k, v, ao);

    dim3 go(EMB/128, MR/128);             // 8 x 64
    gemm_out<<<go, 128, GEMM_SMEM>>>(ao, wo, bo, out);
}

// round 17
// speedup vs baseline: 1.0695x; 1.0344x over previous
#include <cuda_runtime.h>
#include <cuda_fp16.h>
#include <cstdint>
#include <cstddef>

#define EMB 1024
#define SEQ 2048
#define NB  4
#define NH  16
#define MR  (NB*SEQ)   // 8192 rows

// static device scratch (allocation-guard safe) — fp16 activations/weights
__device__ __half g_q [(size_t)MR*EMB];
__device__ __half g_k [(size_t)MR*EMB];
__device__ __half g_v [(size_t)MR*EMB];
__device__ __half g_ao[(size_t)MR*EMB];
__device__ __half g_xc[(size_t)MR*EMB];
__device__ __half g_wq[(size_t)EMB*EMB];
__device__ __half g_wk[(size_t)EMB*EMB];
__device__ __half g_wv[(size_t)EMB*EMB];
__device__ __half g_wo[(size_t)EMB*EMB];

__device__ __forceinline__ float ex2f(float x){
    float y; asm("ex2.approx.ftz.f32 %0, %1;" : "=f"(y) : "f"(x)); return y;
}
// D += A*B : m16n8k16 fp16 in / fp32 accum.
__device__ __forceinline__ void mma16(float* d, const uint32_t* a,
                                      uint32_t b0, uint32_t b1){
    asm volatile(
      "mma.sync.aligned.m16n8k16.row.col.f32.f16.f16.f32 "
      "{%0,%1,%2,%3}, {%4,%5,%6,%7}, {%8,%9}, {%0,%1,%2,%3};\n"
      : "+f"(d[0]), "+f"(d[1]), "+f"(d[2]), "+f"(d[3])
      : "r"(a[0]), "r"(a[1]), "r"(a[2]), "r"(a[3]), "r"(b0), "r"(b1));
}
__device__ __forceinline__ void ldsm4(uint32_t* r, uint32_t saddr){
    asm volatile("ldmatrix.sync.aligned.m8n8.x4.shared.b16 {%0,%1,%2,%3}, [%4];"
        : "=r"(r[0]), "=r"(r[1]), "=r"(r[2]), "=r"(r[3]) : "r"(saddr));
}
__device__ __forceinline__ void ldsm4t(uint32_t* r, uint32_t saddr){
    asm volatile("ldmatrix.sync.aligned.m8n8.x4.trans.shared.b16 {%0,%1,%2,%3}, [%4];"
        : "=r"(r[0]), "=r"(r[1]), "=r"(r[2]), "=r"(r[3]) : "r"(saddr));
}
__device__ __forceinline__ void cpa16(uint32_t saddr, const void* g){
    asm volatile("cp.async.ca.shared.global [%0], [%1], 16;" :: "r"(saddr), "l"(g));
}
__device__ __forceinline__ void cpa_commit(){ asm volatile("cp.async.commit_group;"); }
__device__ __forceinline__ void cpa_wait0(){ asm volatile("cp.async.wait_group 0;"); }
__device__ __forceinline__ void cpa_wait1(){ asm volatile("cp.async.wait_group 1;"); }
__device__ __forceinline__ uint32_t ph2(float lo, float hi){
    __half2 t = __floats2half2_rn(lo, hi);
    return *(uint32_t*)&t;
}

// ------------------------------------------------------------------
// Fused fp32 -> fp16 pre-round: one launch for x + 4 weights.
// ------------------------------------------------------------------
#define CVT_CH 262144   // float4 per chunk

__global__ void __launch_bounds__(256) cvt_all(
    const float4* __restrict__ x,
    const float4* __restrict__ Wq, const float4* __restrict__ Wk,
    const float4* __restrict__ Wv, const float4* __restrict__ Wo,
    uint2* __restrict__ xc,
    uint2* __restrict__ wq, uint2* __restrict__ wk,
    uint2* __restrict__ wv, uint2* __restrict__ wo)
{
    const int c = blockIdx.y;
    const float4* s; uint2* d;
    if (c < 8){ s = x + (size_t)c*CVT_CH; d = xc + (size_t)c*CVT_CH; }
    else if (c == 8){ s = Wq; d = wq; }
    else if (c == 9){ s = Wk; d = wk; }
    else if (c == 10){ s = Wv; d = wv; }
    else { s = Wo; d = wo; }

    int i0 = blockIdx.x*256 + threadIdx.x;
    int i1 = i0 + CVT_CH/2;
    float4 v0 = s[i0];
    float4 v1 = s[i1];
    uint2 o0, o1;
    o0.x = ph2(v0.x, v0.y); o0.y = ph2(v0.z, v0.w);
    o1.x = ph2(v1.x, v1.y); o1.y = ph2(v1.z, v1.w);
    d[i0] = o0;
    d[i1] = o1;
}

// ------------------------------------------------------------------
// fp16 GEMM (R14 structure): C[M,N] = A[M,K] @ W[N,K]^T (+bias).
// Block 128x128, BK=64, 128 thr (4 warps 2m x 2n, warp tile 64x64).
// 2-stage cp.async double buffer, stage AFTER compute (R14 ordering).
// __launch_bounds__(128, 3): 3 CTAs/SM (221KB smem, 170-reg cap) ->
// 12 warps/SM (3/SMSP) to hide ldsm->mma latency.
// ------------------------------------------------------------------
#define RS   144                              // row stride bytes
#define GT_B (128*RS)                         // 18432 per operand tile
#define GSTG (2*GT_B)                         // 36864 per stage
#define GEMM_SMEM (2*GSTG)                    // 73728

__device__ __forceinline__ void gemm_body(
    const __half* __restrict__ A, const __half* __restrict__ W,
    const float* __restrict__ bias, void* __restrict__ C, int out_half)
{
    extern __shared__ uint32_t sh[];
    const uint32_t sbase = (uint32_t)__cvta_generic_to_shared(sh);

    const int tid  = threadIdx.x;
    const int lane = tid & 31, g = lane >> 2, tg = lane & 3;
    const int wid  = tid >> 5;                // 0..3
    const int wm   = (wid & 1) * 64;
    const int wn   = (wid >> 1) * 64;
    const int bm   = blockIdx.y * 128;
    const int bn   = blockIdx.x * 128;

    const int alr = lane & 15;
    const int alk = (lane >> 4) * 16;

    const __half* Ag = A + (size_t)bm*EMB;
    const __half* Wg = W + (size_t)bn*EMB;

    float acc[4][8][4];
#pragma unroll
    for (int mi = 0; mi < 4; mi++)
#pragma unroll
        for (int t = 0; t < 8; t++)
#pragma unroll
            for (int j = 0; j < 4; j++) acc[mi][t][j] = 0.f;

    auto stage = [&](int kt, int s){
        const uint32_t sa = sbase + (uint32_t)s*GSTG;
        const uint32_t sb = sa + GT_B;
#pragma unroll
        for (int i = 0; i < 8; i++){           // A: 128 rows x 8 chunks
            int id = tid + i*128, r = id >> 3, c = id & 7;
            cpa16(sa + r*RS + c*16, Ag + (size_t)r*EMB + kt*64 + c*8);
        }
#pragma unroll
        for (int i = 0; i < 8; i++){           // B: 128 rows x 8 chunks
            int id = tid + i*128, r = id >> 3, c = id & 7;
            cpa16(sb + r*RS + c*16, Wg + (size_t)r*EMB + kt*64 + c*8);
        }
        cpa_commit();
    };

    stage(0, 0);
    stage(1, 1);

    const int nk = EMB/64;   // 16
    for (int kt = 0; kt < nk; kt++){
        const int s = kt & 1;
        if (kt + 1 < nk) cpa_wait1(); else cpa_wait0();
        __syncthreads();
        const uint32_t sa = sbase + (uint32_t)s*GSTG;
        const uint32_t sb = sa + GT_B;
#pragma unroll
        for (int kk = 0; kk < 4; kk++){        // 4 x k16
            uint32_t af[4][4], bf[4][4];
#pragma unroll
            for (int mi = 0; mi < 4; mi++)
                ldsm4(af[mi], sa + (wm + mi*16 + alr)*RS + kk*32 + alk);
#pragma unroll
            for (int p = 0; p < 4; p++)
                ldsm4(bf[p], sb + (wn + p*16 + alr)*RS + kk*32 + alk);
#pragma unroll
            for (int mi = 0; mi < 4; mi++)
#pragma unroll
                for (int p = 0; p < 4; p++){
                    mma16(acc[mi][2*p],   af[mi], bf[p][0], bf[p][2]);
                    mma16(acc[mi][2*p+1], af[mi], bf[p][1], bf[p][3]);
                }
        }
        __syncthreads();
        if (kt + 2 < nk) stage(kt + 2, s);
    }

    // epilogue
#pragma unroll
    for (int mi = 0; mi < 4; mi++){
#pragma unroll
        for (int t = 0; t < 8; t++){
            int col  = bn + wn + t*8 + 2*tg;
            int row0 = bm + wm + mi*16 + g;
            if (out_half){
                __half2 h0 = __floats2half2_rn(acc[mi][t][0], acc[mi][t][1]);
                __half2 h1 = __floats2half2_rn(acc[mi][t][2], acc[mi][t][3]);
                *(__half2*)((__half*)C + (size_t)row0      *EMB + col) = h0;
                *(__half2*)((__half*)C + (size_t)(row0 + 8)*EMB + col) = h1;
            } else {
                float b0 = bias ? bias[col]   : 0.f;
                float b1 = bias ? bias[col+1] : 0.f;
                float2 v0 = make_float2(acc[mi][t][0] + b0, acc[mi][t][1] + b1);
                float2 v1 = make_float2(acc[mi][t][2] + b0, acc[mi][t][3] + b1);
                *(float2*)((float*)C + (size_t)row0      *EMB + col) = v0;
                *(float2*)((float*)C + (size_t)(row0 + 8)*EMB + col) = v1;
            }
        }
    }
}

__global__ void __launch_bounds__(128, 3) gemm_qkv(
    const __half* __restrict__ x,
    const __half* __restrict__ Wq, const __half* __restrict__ Wk,
    const __half* __restrict__ Wv,
    __half* __restrict__ q, __half* __restrict__ k, __half* __restrict__ v)
{
    const __half* W = (blockIdx.z == 0) ? Wq : (blockIdx.z == 1) ? Wk : Wv;
    __half*       C = (blockIdx.z == 0) ? q  : (blockIdx.z == 1) ? k  : v;
    gemm_body(x, W, nullptr, C, 1);
}
__global__ void __launch_bounds__(128, 3) gemm_out(
    const __half* __restrict__ A, const __half* __restrict__ W,
    const float* __restrict__ bias, float* __restrict__ C)
{
    gemm_body(A, W, bias, C, 0);
}

// ------------------------------------------------------------------
// Flash attention v2 (causal) — byte-for-byte R14.
// grid(16, B*H), 256 threads (8 warps), q-tile 128, 16 q-rows/warp.
// Q fragments hoisted; K/V double-buffered; PV via ldmatrix.trans.
// ------------------------------------------------------------------
#define QS_B (128*RS)      // 18432
#define KS_B (64*RS)       //  9216
#define ATTN_SMEM (QS_B + 4*KS_B)   // 55296

__global__ void __launch_bounds__(256, 2) attn_kernel(
    const __half* __restrict__ Q, const __half* __restrict__ K,
    const __half* __restrict__ V, __half* __restrict__ O)
{
    extern __shared__ uint32_t dyn[];
    const uint32_t sbase = (uint32_t)__cvta_generic_to_shared(dyn);
    const uint32_t qsa = sbase;

    const int tid  = threadIdx.x;
    const int lane = tid & 31, g = lane >> 2, tg = lane & 3;
    const int wq   = tid >> 5;
    const int qt   = gridDim.x - 1 - blockIdx.x;    // heavy blocks first
    const int b    = blockIdx.y >> 4;
    const int h    = blockIdx.y & 15;
    const int qbase = qt * 128;
    const float cs = 0.125f * 1.44269504088896f;    // 1/sqrt(64)*log2(e)

    const int alr = lane & 15, alk = (lane >> 4) * 16;

    const __half* Qg = Q + (size_t)(b*SEQ + qbase)*EMB + h*64;
    const __half* Kg = K + (size_t)(b*SEQ)*EMB + h*64;
    const __half* Vg = V + (size_t)(b*SEQ)*EMB + h*64;

    auto kbuf = [&](int s){ return sbase + QS_B + (uint32_t)s*KS_B; };
    auto vbuf = [&](int s){ return sbase + QS_B + 2*KS_B + (uint32_t)s*KS_B; };

    auto load_kv = [&](int jt, int s){
        uint32_t ka = kbuf(s), va = vbuf(s);
#pragma unroll
        for (int i = 0; i < 2; i++){
            int id = tid + i*256, r = id >> 3, c = id & 7;
            cpa16(ka + r*RS + c*16, Kg + (size_t)(jt*64 + r)*EMB + c*8);
        }
#pragma unroll
        for (int i = 0; i < 2; i++){
            int id = tid + i*256, r = id >> 3, c = id & 7;
            cpa16(va + r*RS + c*16, Vg + (size_t)(jt*64 + r)*EMB + c*8);
        }
    };

    const int njt = 2*qt + 2;     // always >= 2

    // prologue: group0 = Q + kv0 ; group1 = kv1 ; retire group0, load qf
#pragma unroll
    for (int i = 0; i < 4; i++){
        int id = tid + i*256, r = id >> 3, c = id & 7;
        cpa16(qsa + r*RS + c*16, Qg + (size_t)r*EMB + c*8);
    }
    load_kv(0, 0);
    cpa_commit();
    load_kv(1, 1);
    cpa_commit();
    cpa_wait1();                 // Q + kv0 arrived (kv1 in flight)
    __syncthreads();

    uint32_t qf[4][4];           // Q A-frags, loop-invariant
#pragma unroll
    for (int ks = 0; ks < 4; ks++)
        ldsm4(qf[ks], qsa + (wq*16 + alr)*RS + ks*32 + alk);

    float m0 = -1e30f, m1 = -1e30f, l0 = 0.f, l1 = 0.f;
    float o[8][4];
#pragma unroll
    for (int t = 0; t < 8; t++)
#pragma unroll
        for (int j = 0; j < 4; j++) o[t][j] = 0.f;

    const int q0r = qbase + wq*16 + g;
    const int q1r = q0r + 8;

    for (int jt = 0; jt < njt; jt++){
        const int s = jt & 1;
        const uint32_t ka = kbuf(s), va = vbuf(s);

        // ---- S = Q @ K^T : 16 q-rows x 64 keys per warp (raw scores)
        float sacc[8][4];
#pragma unroll
        for (int t = 0; t < 8; t++)
#pragma unroll
            for (int j = 0; j < 4; j++) sacc[t][j] = 0.f;
#pragma unroll
        for (int ks = 0; ks < 4; ks++){
            uint32_t bk[4][4];
#pragma unroll
            for (int p = 0; p < 4; p++)
                ldsm4(bk[p], ka + (p*16 + alr)*RS + ks*32 + alk);
#pragma unroll
            for (int p = 0; p < 4; p++){
                mma16(sacc[2*p],   qf[ks], bk[p][0], bk[p][2]);
                mma16(sacc[2*p+1], qf[ks], bk[p][1], bk[p][3]);
            }
        }

        // ---- causal mask (raw) + online softmax (max in raw domain)
        const bool need_mask = (jt >= 2*qt);
        {
            float tm0 = -1e30f, tm1 = -1e30f;
#pragma unroll
            for (int t = 0; t < 8; t++){
                float* sc = sacc[t];
                if (need_mask){
                    int jc = jt*64 + t*8 + 2*tg;
                    if (jc     > q0r) sc[0] = -1e30f;
                    if (jc + 1 > q0r) sc[1] = -1e30f;
                    if (jc     > q1r) sc[2] = -1e30f;
                    if (jc + 1 > q1r) sc[3] = -1e30f;
                }
                tm0 = fmaxf(tm0, fmaxf(sc[0], sc[1]));
                tm1 = fmaxf(tm1, fmaxf(sc[2], sc[3]));
            }
            tm0 = fmaxf(tm0, __shfl_xor_sync(0xffffffffu, tm0, 1));
            tm0 = fmaxf(tm0, __shfl_xor_sync(0xffffffffu, tm0, 2));
            tm1 = fmaxf(tm1, __shfl_xor_sync(0xffffffffu, tm1, 1));
            tm1 = fmaxf(tm1, __shfl_xor_sync(0xffffffffu, tm1, 2));
            float mn0 = fmaxf(m0, tm0 * cs);
            float mn1 = fmaxf(m1, tm1 * cs);
            float a0  = ex2f(m0 - mn0);
            float a1  = ex2f(m1 - mn1);
            float rs0 = 0.f, rs1 = 0.f;
#pragma unroll
            for (int t = 0; t < 8; t++){
                float* sc = sacc[t];
                sc[0] = ex2f(fmaf(sc[0], cs, -mn0));
                sc[1] = ex2f(fmaf(sc[1], cs, -mn0));
                sc[2] = ex2f(fmaf(sc[2], cs, -mn1));
                sc[3] = ex2f(fmaf(sc[3], cs, -mn1));
                rs0 += sc[0] + sc[1];
                rs1 += sc[2] + sc[3];
            }
            rs0 += __shfl_xor_sync(0xffffffffu, rs0, 1);
            rs0 += __shfl_xor_sync(0xffffffffu, rs0, 2);
            rs1 += __shfl_xor_sync(0xffffffffu, rs1, 1);
            rs1 += __shfl_xor_sync(0xffffffffu, rs1, 2);
            l0 = l0*a0 + rs0;
            l1 = l1*a1 + rs1;
            m0 = mn0; m1 = mn1;
#pragma unroll
            for (int t = 0; t < 8; t++){
                o[t][0] *= a0; o[t][1] *= a0;
                o[t][2] *= a1; o[t][3] *= a1;
            }
        }

        // ---- O += P @ V : B-frags via ldmatrix.trans on row-major V
#pragma unroll
        for (int ks = 0; ks < 4; ks++){
            uint32_t av[4];
            av[0] = ph2(sacc[2*ks][0],   sacc[2*ks][1]);
            av[1] = ph2(sacc[2*ks][2],   sacc[2*ks][3]);
            av[2] = ph2(sacc[2*ks+1][0], sacc[2*ks+1][1]);
            av[3] = ph2(sacc[2*ks+1][2], sacc[2*ks+1][3]);
#pragma unroll
            for (int p = 0; p < 4; p++){
                uint32_t bv[4];
                ldsm4t(bv, va + (ks*16 + alr)*RS + p*32 + alk);
                mma16(o[2*p],   av, bv[0], bv[1]);
                mma16(o[2*p+1], av, bv[2], bv[3]);
            }
        }

        // ---- pipeline: free buffer s, prefetch jt+2, ensure jt+1 arrived
        __syncthreads();
        if (jt + 1 < njt){
            if (jt + 2 < njt){ load_kv(jt + 2, s); cpa_commit(); cpa_wait1(); }
            else             { cpa_wait0(); }
            __syncthreads();
        }
    }

    // ---- epilogue: normalize, store half (feeds final GEMM)
    {
        float i0 = 1.f / l0;
        float i1 = 1.f / l1;
        size_t r0 = (size_t)(b*SEQ + q0r);
#pragma unroll
        for (int t = 0; t < 8; t++){
            int col = h*64 + t*8 + 2*tg;
            __half2 h0 = __floats2half2_rn(o[t][0]*i0, o[t][1]*i0);
            __half2 h1 = __floats2half2_rn(o[t][2]*i1, o[t][3]*i1);
            *(__half2*)(O + r0*EMB + col)       = h0;
            *(__half2*)(O + (r0 + 8)*EMB + col) = h1;
        }
    }
}

// ------------------------------------------------------------------
extern "C" void kernel_launch(void* const* d_in, const int* in_sizes, int n_in,
                              void* d_out, int out_size)
{
    const float* x  = (const float*)d_in[0];
    const float* Wq = (const float*)d_in[1];
    const float* Wk = (const float*)d_in[2];
    const float* Wv = (const float*)d_in[3];
    const float* Wo = (const float*)d_in[4];
    const float* bo = (const float*)d_in[5];
    float* out = (float*)d_out;

    __half *q, *k, *v, *ao, *xc, *wq, *wk, *wv, *wo;
    cudaGetSymbolAddress((void**)&q,  g_q);
    cudaGetSymbolAddress((void**)&k,  g_k);
    cudaGetSymbolAddress((void**)&v,  g_v);
    cudaGetSymbolAddress((void**)&ao, g_ao);
    cudaGetSymbolAddress((void**)&xc, g_xc);
    cudaGetSymbolAddress((void**)&wq, g_wq);
    cudaGetSymbolAddress((void**)&wk, g_wk);
    cudaGetSymbolAddress((void**)&wv, g_wv);
    cudaGetSymbolAddress((void**)&wo, g_wo);

    cudaFuncSetAttribute(gemm_qkv,
                         cudaFuncAttributeMaxDynamicSharedMemorySize, GEMM_SMEM);
    cudaFuncSetAttribute(gemm_out,
                         cudaFuncAttributeMaxDynamicSharedMemorySize, GEMM_SMEM);
    cudaFuncSetAttribute(attn_kernel,
                         cudaFuncAttributeMaxDynamicSharedMemorySize, ATTN_SMEM);

    // fused fp32->fp16 pre-round (x: 8 chunks, weights: 1 chunk each)
    dim3 gc(CVT_CH/(256*2), 12);          // 512 x 12
    cvt_all<<<gc, 256>>>((const float4*)x,
                         (const float4*)Wq, (const float4*)Wk,
                         (const float4*)Wv, (const float4*)Wo,
                         (uint2*)xc, (uint2*)wq, (uint2*)wk,
                         (uint2*)wv, (uint2*)wo);

    dim3 gq(EMB/128, MR/128, 3);          // 8 x 64 x 3
    gemm_qkv<<<gq, 128, GEMM_SMEM>>>(xc, wq, wk, wv, q, k, v);

    dim3 ga(SEQ/128, NB*NH);              // 16 x 64
    attn_kernel<<<ga, 256, ATTN_SMEM>>>(q, k, v, ao);

    dim3 go(EMB/128, MR/128);             // 8 x 64
    gemm_out<<<go, 128, GEMM_SMEM>>>(ao, wo, bo, out);
}